// round 14
// baseline (speedup 1.0000x reference)
#include <cuda_runtime.h>
#include <cuda_bf16.h>
#include <math.h>
#include <stdint.h>

#define B_  16
#define C_  256
#define T_  2048
#define CQK_ 32
#define LOG2E_F 1.4426950408889634f

// Scratch (allocation-free rule: __device__ globals)
__device__ float g_Q[B_ * CQK_ * T_];            // [B][32][T] tf32, pre-scaled log2e
__device__ float g_K[B_ * T_ * CQK_];            // [B][T][32] transposed, tf32
__device__ __nv_bfloat16 g_V[B_ * C_ * T_];      // [B][256][T] bf16
__device__ float g_Wtf[C_ * C_];                 // Wv, tf32-RNA rounded

// ===========================================================================
// helpers
// ===========================================================================
__device__ __forceinline__ uint32_t smem_u32(const void* p) {
    uint32_t a;
    asm("{ .reg .u64 t; cvta.to.shared.u64 t, %1; cvt.u32.u64 %0, t; }"
        : "=r"(a) : "l"(p));
    return a;
}
__device__ __forceinline__ float tf32_rna(float f) {
    uint32_t u;
    asm("cvt.rna.tf32.f32 %0, %1;" : "=r"(u) : "f"(f));
    return __uint_as_float(u);
}
__device__ __forceinline__ float ex2f(float x) {
    float r;
    asm("ex2.approx.f32 %0, %1;" : "=f"(r) : "f"(x));
    return r;
}
// pack: lo = b, hi = a
__device__ __forceinline__ uint32_t bf16x2_pack(float hi, float lo) {
    uint32_t r;
    asm("cvt.rn.bf16x2.f32 %0, %1, %2;" : "=r"(r) : "f"(hi), "f"(lo));
    return r;
}
__device__ __forceinline__ void mma_tf32(float d[4], const float a[4],
                                         float b0, float b1) {
    asm volatile(
        "mma.sync.aligned.m16n8k8.row.col.f32.tf32.tf32.f32 "
        "{%0,%1,%2,%3}, {%4,%5,%6,%7}, {%8,%9}, {%0,%1,%2,%3};"
        : "+f"(d[0]), "+f"(d[1]), "+f"(d[2]), "+f"(d[3])
        : "r"(__float_as_uint(a[0])), "r"(__float_as_uint(a[1])),
          "r"(__float_as_uint(a[2])), "r"(__float_as_uint(a[3])),
          "r"(__float_as_uint(b0)),  "r"(__float_as_uint(b1)));
}
__device__ __forceinline__ void mma_bf16(float d[4], uint32_t a0, uint32_t a1,
                                         uint32_t a2, uint32_t a3,
                                         uint32_t b0, uint32_t b1) {
    asm volatile(
        "mma.sync.aligned.m16n8k16.row.col.f32.bf16.bf16.f32 "
        "{%0,%1,%2,%3}, {%4,%5,%6,%7}, {%8,%9}, {%0,%1,%2,%3};"
        : "+f"(d[0]), "+f"(d[1]), "+f"(d[2]), "+f"(d[3])
        : "r"(a0), "r"(a1), "r"(a2), "r"(a3), "r"(b0), "r"(b1));
}
#define CP_ASYNC16(dst, src) \
    asm volatile("cp.async.ca.shared.global [%0], [%1], 16;" \
        :: "r"(dst), "l"(src) : "memory")
#define CP_COMMIT() asm volatile("cp.async.commit_group;" ::: "memory")
#define BAR_PAIR(id) \
    asm volatile("bar.sync %0, %1;" :: "r"(id), "r"(64) : "memory")

// ===========================================================================
// W prepack: tf32-RNA round Wv into g_Wtf (avoids tf32 truncation bias)
// ===========================================================================
__global__ void wpack_kernel(const float* __restrict__ Wv) {
    const int i = blockIdx.x * 256 + threadIdx.x;
    g_Wtf[i] = tf32_rna(Wv[i]);
}

// ===========================================================================
// Projection (FFMA) for Q and K only.
// mode 0: fp32 [O][T] tf32-rounded (Q, scaled).  mode 1: fp32 [T][32] (K).
// ===========================================================================
__global__ void __launch_bounds__(256) proj_kernel(
    const float* __restrict__ x, const float* __restrict__ W,
    const float* __restrict__ bias, void* __restrict__ yv, int O, float scale,
    int mode)
{
    __shared__ float Ws[32 * 33];
    __shared__ float xs[32 * 132];

    const int t0 = blockIdx.x * 128;
    const int o0 = blockIdx.y * 32;
    const int b  = blockIdx.z;
    const int tid = threadIdx.x;
    const int oi = tid >> 5;
    const int ti = tid & 31;

    float acc[4][4];
#pragma unroll
    for (int a = 0; a < 4; a++)
#pragma unroll
        for (int bb = 0; bb < 4; bb++) acc[a][bb] = 0.f;

    for (int k0 = 0; k0 < C_; k0 += 32) {
#pragma unroll
        for (int k = 0; k < 4; k++) {
            int idx = tid + 256 * k;
            int o = idx >> 5, c = idx & 31;
            Ws[o * 33 + c] = W[(o0 + o) * C_ + k0 + c];
        }
#pragma unroll
        for (int k = 0; k < 4; k++) {
            int f = tid + 256 * k;
            int c = f >> 5, t4 = f & 31;
            const float4 v = *(const float4*)&x[((size_t)b * C_ + (k0 + c)) * T_ + t0 + t4 * 4];
            *(float4*)&xs[c * 132 + t4 * 4] = v;
        }
        __syncthreads();

#pragma unroll 8
        for (int c = 0; c < 32; c++) {
            float w[4], xv[4];
#pragma unroll
            for (int a = 0; a < 4; a++) w[a] = Ws[(oi * 4 + a) * 33 + c];
#pragma unroll
            for (int bb = 0; bb < 4; bb++) xv[bb] = xs[c * 132 + ti + 32 * bb];
#pragma unroll
            for (int a = 0; a < 4; a++)
#pragma unroll
                for (int bb = 0; bb < 4; bb++) acc[a][bb] += w[a] * xv[bb];
        }
        __syncthreads();
    }

    if (mode == 1) {
        float* y = (float*)yv;
        float bo[4];
#pragma unroll
        for (int a = 0; a < 4; a++) bo[a] = bias[oi * 4 + a];
#pragma unroll
        for (int bb = 0; bb < 4; bb++) {
            const int t = t0 + ti + 32 * bb;
            float4 v;
            v.x = tf32_rna((acc[0][bb] + bo[0]) * scale);
            v.y = tf32_rna((acc[1][bb] + bo[1]) * scale);
            v.z = tf32_rna((acc[2][bb] + bo[2]) * scale);
            v.w = tf32_rna((acc[3][bb] + bo[3]) * scale);
            *(float4*)&y[((size_t)b * T_ + t) * 32 + oi * 4] = v;
        }
    } else {
        float* y = (float*)yv;
#pragma unroll
        for (int a = 0; a < 4; a++) {
            const int o = o0 + oi * 4 + a;
            const float bo = bias[o];
#pragma unroll
            for (int bb = 0; bb < 4; bb++) {
                const int t = t0 + ti + 32 * bb;
                y[((size_t)b * O + o) * T_ + t] = tf32_rna((acc[a][bb] + bo) * scale);
            }
        }
    }
}

// ===========================================================================
// V projection (tf32 mma) — unchanged from R13 (56us, verified).
// ===========================================================================
#define XP_STRIDE 48
#define XP_BYTES (128 * XP_STRIDE * 4)      // 24576
#define WP_STRIDE 48
#define WP_BYTES (256 * WP_STRIDE * 4)      // 49152
#define VP_BUF (XP_BYTES + WP_BYTES)        // 73728
#define VP_SMEM (2 * VP_BUF)                // 147456

__global__ void __launch_bounds__(512, 1) vproj_mma_kernel(
    const float* __restrict__ x, const float* __restrict__ bv,
    __nv_bfloat16* __restrict__ V)
{
    extern __shared__ char smem[];
    const uint32_t sb = smem_u32(smem);
    const int tid = threadIdx.x;
    const int wid = tid >> 5, lid = tid & 31;
    const int g = lid >> 2, tig = lid & 3;
    const int rg = wid & 7;
    const int oh = wid >> 3;
    const int b = blockIdx.y;
    const int t0 = blockIdx.x * 128;

    const int xc = lid;
    const int xtq0 = wid, xtq1 = wid + 16;
    const float* xb = x + (size_t)b * C_ * T_ + t0;

    const int xs_a = ((rg * 16 + g) * XP_STRIDE + 4 * tig) * 4;
    const int ws_b = ((oh * 128 + g) * WP_STRIDE + 4 * tig) * 4;

    const uint32_t u0 = sb, u1 = sb + VP_BUF;
    const uint32_t sts0 = (uint32_t)((4 * xtq0) * XP_STRIDE + xc) * 4;
    const uint32_t sts1 = (uint32_t)((4 * xtq1) * XP_STRIDE + xc) * 4;

    float4 xr[2];
    float acc[16][4];
#pragma unroll
    for (int nb = 0; nb < 16; nb++)
#pragma unroll
        for (int e = 0; e < 4; e++) acc[nb][e] = 0.f;

    xr[0] = *(const float4*)(xb + (size_t)xc * T_ + 4 * xtq0);
    xr[1] = *(const float4*)(xb + (size_t)xc * T_ + 4 * xtq1);
    {
#pragma unroll
        for (int j = 0; j < 4; j++) {
            const int idx = tid + j * 512;
            const int o = idx >> 3, q = idx & 7;
            CP_ASYNC16(u0 + XP_BYTES + o * (WP_STRIDE * 4) + q * 16,
                       g_Wtf + (size_t)o * C_ + 4 * q);
        }
        CP_COMMIT();
    }

#pragma unroll
    for (int ch = 0; ch < 8; ch++) {
        const uint32_t ub = (ch & 1) ? u1 : u0;
        {
            const uint32_t a0 = ub + sts0;
            asm volatile("st.shared.f32 [%0], %1;"     :: "r"(a0), "f"(xr[0].x));
            asm volatile("st.shared.f32 [%0+192], %1;" :: "r"(a0), "f"(xr[0].y));
            asm volatile("st.shared.f32 [%0+384], %1;" :: "r"(a0), "f"(xr[0].z));
            asm volatile("st.shared.f32 [%0+576], %1;" :: "r"(a0), "f"(xr[0].w));
            const uint32_t a1 = ub + sts1;
            asm volatile("st.shared.f32 [%0], %1;"     :: "r"(a1), "f"(xr[1].x));
            asm volatile("st.shared.f32 [%0+192], %1;" :: "r"(a1), "f"(xr[1].y));
            asm volatile("st.shared.f32 [%0+384], %1;" :: "r"(a1), "f"(xr[1].z));
            asm volatile("st.shared.f32 [%0+576], %1;" :: "r"(a1), "f"(xr[1].w));
        }
        if (ch + 1 < 8) {
            const int cnext = (ch + 1) * 32 + xc;
            xr[0] = *(const float4*)(xb + (size_t)cnext * T_ + 4 * xtq0);
            xr[1] = *(const float4*)(xb + (size_t)cnext * T_ + 4 * xtq1);
            const uint32_t un = (ch & 1) ? u0 : u1;
#pragma unroll
            for (int j = 0; j < 4; j++) {
                const int idx = tid + j * 512;
                const int o = idx >> 3, q = idx & 7;
                CP_ASYNC16(un + XP_BYTES + o * (WP_STRIDE * 4) + q * 16,
                           g_Wtf + (size_t)o * C_ + (ch + 1) * 32 + 4 * q);
            }
            CP_COMMIT();
            asm volatile("cp.async.wait_group 1;" ::: "memory");
        } else {
            asm volatile("cp.async.wait_group 0;" ::: "memory");
        }
        __syncthreads();

        const char* sc = smem + (size_t)(ch & 1) * VP_BUF;
        const char* ax = sc + xs_a;
        const float4 fa0 = *(const float4*)(ax);
        const float4 fa1 = *(const float4*)(ax + 8 * XP_STRIDE * 4);
        const float4 fa2 = *(const float4*)(ax + 64);
        const float4 fa3 = *(const float4*)(ax + 8 * XP_STRIDE * 4 + 64);
        float aF[4][4];
        aF[0][0] = tf32_rna(fa0.x); aF[0][1] = tf32_rna(fa1.x);
        aF[0][2] = tf32_rna(fa2.x); aF[0][3] = tf32_rna(fa3.x);
        aF[1][0] = tf32_rna(fa0.y); aF[1][1] = tf32_rna(fa1.y);
        aF[1][2] = tf32_rna(fa2.y); aF[1][3] = tf32_rna(fa3.y);
        aF[2][0] = tf32_rna(fa0.z); aF[2][1] = tf32_rna(fa1.z);
        aF[2][2] = tf32_rna(fa2.z); aF[2][3] = tf32_rna(fa3.z);
        aF[3][0] = tf32_rna(fa0.w); aF[3][1] = tf32_rna(fa1.w);
        aF[3][2] = tf32_rna(fa2.w); aF[3][3] = tf32_rna(fa3.w);

        const char* bw = sc + XP_BYTES + ws_b;
#pragma unroll
        for (int nb = 0; nb < 16; nb++) {
            const float4 blo = *(const float4*)(bw + nb * 8 * (WP_STRIDE * 4));
            const float4 bhi = *(const float4*)(bw + nb * 8 * (WP_STRIDE * 4) + 64);
            mma_tf32(acc[nb], aF[0], blo.x, bhi.x);
            mma_tf32(acc[nb], aF[1], blo.y, bhi.y);
            mma_tf32(acc[nb], aF[2], blo.z, bhi.z);
            mma_tf32(acc[nb], aF[3], blo.w, bhi.w);
        }
        __syncthreads();
    }

    float* Osm = (float*)smem;
    __nv_bfloat16* Vb = V + (size_t)b * C_ * T_ + t0;
    for (int r = 0; r < 4; r++) {
        __syncthreads();
        if ((r >> 1) == oh) {
            const int nbb = (r & 1) * 8;
            const int tl = rg * 16 + g;
#pragma unroll
            for (int nbl = 0; nbl < 8; nbl++) {
                const int nb = nbb + nbl;
                const int o2 = nbl * 8 + 2 * tig;
                Osm[(o2 + 0) * 132 + tl]     = acc[nb][0];
                Osm[(o2 + 1) * 132 + tl]     = acc[nb][1];
                Osm[(o2 + 0) * 132 + tl + 8] = acc[nb][2];
                Osm[(o2 + 1) * 132 + tl + 8] = acc[nb][3];
            }
        }
        __syncthreads();
#pragma unroll
        for (int k = 0; k < 4; k++) {
            const int idx = tid + k * 512;
            const int op = idx >> 5, tq = idx & 31;
            float4 v = *(const float4*)&Osm[op * 132 + tq * 4];
            const float bo = __ldg(&bv[r * 64 + op]);
            v.x += bo; v.y += bo; v.z += bo; v.w += bo;
            uint2 st;
            st.x = bf16x2_pack(v.y, v.x);
            st.y = bf16x2_pack(v.w, v.z);
            *(uint2*)&Vb[(size_t)(r * 64 + op) * T_ + tq * 4] = st;
        }
    }
}

// ===========================================================================
// Attention v9: software-pipelined (MMA1(it+1) overlapped with MMA2(it)).
//  512 threads, 16 warps = 8 rowgroups(16 rows) x 2 col-halves.
//  4-stage cp.async ring (reads span it, it+1); double-buffered P tile.
// ===========================================================================
#define KT_STRIDE 48
#define KT_BYTES (32 * KT_STRIDE * 4)       // 6144
#define VS_STRIDE_B 64
#define VS_BYTES (256 * VS_STRIDE_B)        // 16384
#define STAGE_BYTES (KT_BYTES + VS_BYTES)   // 22528
#define PS_OFF  (4 * STAGE_BYTES)           // 90112
#define PS_STRIDE_B 80
#define PS_BYTES (128 * PS_STRIDE_B)        // 10240
#define LS_OFF  (PS_OFF + 2 * PS_BYTES)     // 110592
#define SMEM_BYTES (LS_OFF + 1024)          // 111616

#define MMA1_4(sdrow, aq, lo, hi) \
    mma_tf32(sdrow, aq[0], lo.x, hi.x); \
    mma_tf32(sdrow, aq[1], lo.y, hi.y); \
    mma_tf32(sdrow, aq[2], lo.z, hi.z); \
    mma_tf32(sdrow, aq[3], lo.w, hi.w);

__global__ void __launch_bounds__(512, 1) attn_mma_kernel(
    const float* __restrict__ x, float* __restrict__ out)
{
    extern __shared__ char smem[];
    const uint32_t sb = smem_u32(smem);

    const int tid = threadIdx.x;
    const int wid = tid >> 5, lid = tid & 31;
    const int g   = lid >> 2, tig = lid & 3;
    const int rg  = wid & 7;
    const int ch  = wid >> 3;
    const int b  = blockIdx.y;
    const int t0 = blockIdx.x * 128;
    const int prow = rg * 16;

    const int krow = (tid & 255) >> 3, chn8 = tid & 7;
    const uint32_t k_dst = (uint32_t)(krow * (KT_STRIDE * 4) + chn8 * 16);
    const float* kg = &g_K[(size_t)b * T_ * CQK_] + (size_t)krow * CQK_ + chn8 * 4;
    const int vrow = tid >> 1, vhalf = tid & 1;
    const uint32_t v_dst = (uint32_t)(KT_BYTES + vrow * VS_STRIDE_B + vhalf * 32);
    const __nv_bfloat16* vg = &g_V[(size_t)b * C_ * T_] + (size_t)vrow * T_ + vhalf * 16;

    const int kf_off = ((ch * 16 + g) * KT_STRIDE + 4 * tig) * 4;
    const int vf_off = KT_BYTES + (ch * 128 + g) * VS_STRIDE_B + 16 * tig;

    // P double buffer: A at PS_OFF, B at PS_OFF + PS_BYTES
    const uint32_t ps_woff = (uint32_t)((prow + g) * PS_STRIDE_B + 32 * ch + 4 * tig);
    const int      ps_roff = (prow + g) * PS_STRIDE_B + 16 * tig;
    uint32_t pw_cur = sb + PS_OFF + PS_BYTES + ps_woff;          // writes P(it+1) -> B first
    uint32_t pw_alt = sb + PS_OFF + ps_woff;
    const char* pr_cur = smem + PS_OFF + ps_roff;                 // reads P(it) -> A first
    const char* pr_alt = smem + PS_OFF + PS_BYTES + ps_roff;

    // 4-deep rotating stage ring
    const char* s0 = smem;
    const char* s1 = smem + STAGE_BYTES;
    const char* s2 = smem + 2 * STAGE_BYTES;
    const char* s3 = smem + 3 * STAGE_BYTES;
    uint32_t u0 = sb, u1 = sb + STAGE_BYTES, u2 = sb + 2 * STAGE_BYTES,
             u3 = sb + 3 * STAGE_BYTES;

    auto stage_to = [&](uint32_t base) {
        if (tid < 256) CP_ASYNC16(base + k_dst, kg);
        kg += 32 * CQK_;
        CP_ASYNC16(base + v_dst,      vg);
        CP_ASYNC16(base + v_dst + 16, vg + 8);
        vg += 32;
        CP_COMMIT();
    };

    stage_to(u0);
    stage_to(u1);
    stage_to(u2);

    float aQ[4][4];
    {
        const float* qb = &g_Q[(size_t)b * CQK_ * T_];
        const int rowb = t0 + prow;
#pragma unroll
        for (int kb = 0; kb < 4; kb++) {
            aQ[kb][0] = qb[(4 * tig + kb) * T_      + rowb + g];
            aQ[kb][1] = qb[(4 * tig + kb) * T_      + rowb + g + 8];
            aQ[kb][2] = qb[(4 * tig + 16 + kb) * T_ + rowb + g];
            aQ[kb][3] = qb[(4 * tig + 16 + kb) * T_ + rowb + g + 8];
        }
    }

    float acc[16][4];
#pragma unroll
    for (int nb = 0; nb < 16; nb++)
#pragma unroll
        for (int e = 0; e < 4; e++) acc[nb][e] = 0.f;
    float lsum0 = 0.f, lsum1 = 0.f;

    const int NSTEP = T_ / 32;   // 64
    const int barid = rg + 1;

    // ---- prologue: MMA1(0) -> P(0) into buffer A ----
    asm volatile("cp.async.wait_group 2;" ::: "memory");  // stage(0) done
    __syncthreads();
    {
        const char* Kw = s0 + kf_off;
        float sd[2][4];
#pragma unroll
        for (int nbl = 0; nbl < 2; nbl++)
#pragma unroll
            for (int e = 0; e < 4; e++) sd[nbl][e] = 0.f;
        const float4 lo0 = *(const float4*)(Kw);
        const float4 hi0 = *(const float4*)(Kw + 64);
        const float4 lo1 = *(const float4*)(Kw + 8 * KT_STRIDE * 4);
        const float4 hi1 = *(const float4*)(Kw + 8 * KT_STRIDE * 4 + 64);
        MMA1_4(sd[0], aQ, lo0, hi0);
        MMA1_4(sd[1], aQ, lo1, hi1);
#pragma unroll
        for (int nbl = 0; nbl < 2; nbl++) {
            const float p0 = ex2f(sd[nbl][0]);
            const float p1 = ex2f(sd[nbl][1]);
            const float p2 = ex2f(sd[nbl][2]);
            const float p3 = ex2f(sd[nbl][3]);
            const uint32_t pk01 = bf16x2_pack(p1, p0);
            const uint32_t pk23 = bf16x2_pack(p3, p2);
            lsum0 += __uint_as_float(pk01 << 16)
                   + __uint_as_float(pk01 & 0xFFFF0000u);
            lsum1 += __uint_as_float(pk23 << 16)
                   + __uint_as_float(pk23 & 0xFFFF0000u);
            // prologue writes buffer A (= pw_alt)
            const uint32_t w = pw_alt + (uint32_t)(nbl * 16);
            asm volatile("st.shared.b32 [%0], %1;" :: "r"(w), "r"(pk01) : "memory");
            asm volatile("st.shared.b32 [%0+640], %1;" :: "r"(w), "r"(pk23) : "memory");
        }
        BAR_PAIR(barid);
    }

    // ---- pipelined mainloop ----
    for (int it = 0; it < NSTEP; it++) {
        // stage(it+1) (K for MMA1) and stage(it) (V) must be complete
        if (it < 62) {
            asm volatile("cp.async.wait_group 1;" ::: "memory");
        } else {
            asm volatile("cp.async.wait_group 0;" ::: "memory");
        }
        __syncthreads();
        if (it + 3 < NSTEP) stage_to(u3);

        const bool more = (it + 1 < NSTEP);
        float sd[2][4];
        if (more) {
            const char* Kw = s1 + kf_off;
#pragma unroll
            for (int nbl = 0; nbl < 2; nbl++)
#pragma unroll
                for (int e = 0; e < 4; e++) sd[nbl][e] = 0.f;
            const float4 lo0 = *(const float4*)(Kw);
            const float4 hi0 = *(const float4*)(Kw + 64);
            const float4 lo1 = *(const float4*)(Kw + 8 * KT_STRIDE * 4);
            const float4 hi1 = *(const float4*)(Kw + 8 * KT_STRIDE * 4 + 64);
            MMA1_4(sd[0], aQ, lo0, hi0);
            MMA1_4(sd[1], aQ, lo1, hi1);
        }

        // MMA2(it): P(it) from pr_cur, V(it) from s0
        {
            const uint4 pA0 = *(const uint4*)(pr_cur);
            const uint4 pA1 = *(const uint4*)(pr_cur + 8 * PS_STRIDE_B);
            const char* Vw = s0 + vf_off;
#pragma unroll
            for (int nb = 0; nb < 16; nb++) {
                const uint4 vq = *(const uint4*)(Vw + nb * 8 * VS_STRIDE_B);
                mma_bf16(acc[nb], pA0.x, pA1.x, pA0.y, pA1.y, vq.x, vq.y);
                mma_bf16(acc[nb], pA0.z, pA1.z, pA0.w, pA1.w, vq.z, vq.w);
            }
        }

        if (more) {
#pragma unroll
            for (int nbl = 0; nbl < 2; nbl++) {
                const float p0 = ex2f(sd[nbl][0]);
                const float p1 = ex2f(sd[nbl][1]);
                const float p2 = ex2f(sd[nbl][2]);
                const float p3 = ex2f(sd[nbl][3]);
                const uint32_t pk01 = bf16x2_pack(p1, p0);
                const uint32_t pk23 = bf16x2_pack(p3, p2);
                lsum0 += __uint_as_float(pk01 << 16)
                       + __uint_as_float(pk01 & 0xFFFF0000u);
                lsum1 += __uint_as_float(pk23 << 16)
                       + __uint_as_float(pk23 & 0xFFFF0000u);
                const uint32_t w = pw_cur + (uint32_t)(nbl * 16);
                asm volatile("st.shared.b32 [%0], %1;" :: "r"(w), "r"(pk01) : "memory");
                asm volatile("st.shared.b32 [%0+640], %1;" :: "r"(w), "r"(pk23) : "memory");
            }
            BAR_PAIR(barid);
            // swap P buffers
            const uint32_t wtmp = pw_cur; pw_cur = pw_alt; pw_alt = wtmp;
            const char* rtmp = pr_cur; pr_cur = pr_alt; pr_alt = rtmp;
        }

        // rotate 4-ring
        const char* stmp = s0; s0 = s1; s1 = s2; s2 = s3; s3 = stmp;
        const uint32_t utmp = u0; u0 = u1; u1 = u2; u2 = u3; u3 = utmp;
    }

    // ---- combine partial rowsums ----
    lsum0 += __shfl_xor_sync(0xffffffffu, lsum0, 1);
    lsum0 += __shfl_xor_sync(0xffffffffu, lsum0, 2);
    lsum1 += __shfl_xor_sync(0xffffffffu, lsum1, 1);
    lsum1 += __shfl_xor_sync(0xffffffffu, lsum1, 2);
    float* LS = (float*)(smem + LS_OFF);
    __syncthreads();
    LS[(prow + g) * 2 + ch]     = lsum0;
    LS[(prow + 8 + g) * 2 + ch] = lsum1;
    __syncthreads();
    const float inv0 = 1.0f / (LS[(prow + g) * 2]     + LS[(prow + g) * 2 + 1]);
    const float inv1 = 1.0f / (LS[(prow + 8 + g) * 2] + LS[(prow + 8 + g) * 2 + 1]);

    // ---- epilogue: smem transpose per 32-col chunk, coalesced stores ----
    float* Osm = (float*)smem;
    const int tl = prow + g;
    for (int cc = 0; cc < 8; cc++) {
        __syncthreads();
        if ((cc >> 2) == ch) {
#pragma unroll
            for (int nbl = 0; nbl < 4; nbl++) {
                const int nb = (cc & 3) * 4 + nbl;
                const int c0 = nbl * 8 + 2 * tig;
                Osm[(c0 + 0) * 132 + tl]     = acc[nb][0] * inv0;
                Osm[(c0 + 1) * 132 + tl]     = acc[nb][1] * inv0;
                Osm[(c0 + 0) * 132 + tl + 8] = acc[nb][2] * inv1;
                Osm[(c0 + 1) * 132 + tl + 8] = acc[nb][3] * inv1;
            }
        }
        __syncthreads();
#pragma unroll
        for (int k = 0; k < 2; k++) {
            const int i = tid + k * 512;
            const int c = i >> 5;
            const int t4 = i & 31;
            float4 v = *(const float4*)&Osm[c * 132 + t4 * 4];
            const size_t gi = ((size_t)b * C_ + cc * 32 + c) * T_ + t0 + t4 * 4;
            const float4 xv = *(const float4*)&x[gi];
            v.x += xv.x; v.y += xv.y; v.z += xv.z; v.w += xv.w;
            *(float4*)&out[gi] = v;
        }
    }
}

// ===========================================================================
extern "C" void kernel_launch(void* const* d_in, const int* in_sizes, int n_in,
                              void* d_out, int out_size)
{
    const float* x  = (const float*)d_in[0];
    const float* Wq = (const float*)d_in[1];
    const float* bq = (const float*)d_in[2];
    const float* Wk = (const float*)d_in[3];
    const float* bk = (const float*)d_in[4];
    const float* Wv = (const float*)d_in[5];
    const float* bv = (const float*)d_in[6];
    float* out = (float*)d_out;

    void *qp, *kp, *vp;
    cudaGetSymbolAddress(&qp, g_Q);
    cudaGetSymbolAddress(&kp, g_K);
    cudaGetSymbolAddress(&vp, g_V);

    cudaFuncSetAttribute(attn_mma_kernel,
                         cudaFuncAttributeMaxDynamicSharedMemorySize, SMEM_BYTES);
    cudaFuncSetAttribute(vproj_mma_kernel,
                         cudaFuncAttributeMaxDynamicSharedMemorySize, VP_SMEM);

    wpack_kernel<<<C_ * C_ / 256, 256>>>(Wv);
    proj_kernel<<<dim3(T_ / 128, 1, B_), 256>>>(x, Wq, bq, qp, CQK_, LOG2E_F, 0);
    proj_kernel<<<dim3(T_ / 128, 1, B_), 256>>>(x, Wk, bk, kp, CQK_, 1.0f, 1);
    vproj_mma_kernel<<<dim3(T_ / 128, B_), 512, VP_SMEM>>>(
        x, bv, (__nv_bfloat16*)vp);
    attn_mma_kernel<<<dim3(T_ / 128, B_), 512, SMEM_BYTES>>>(x, out);
}

// round 15
// speedup vs baseline: 1.0628x; 1.0628x over previous
#include <cuda_runtime.h>
#include <cuda_bf16.h>
#include <math.h>
#include <stdint.h>

#define B_  16
#define C_  256
#define T_  2048
#define CQK_ 32
#define LOG2E_F 1.4426950408889634f

// Scratch (allocation-free rule: __device__ globals)
__device__ float g_Q[B_ * CQK_ * T_];            // [B][32][T] tf32, pre-scaled log2e
__device__ float g_K[B_ * T_ * CQK_];            // [B][T][32] transposed, tf32
__device__ __nv_bfloat16 g_V[B_ * C_ * T_];      // [B][256][T] bf16
__device__ float g_Wtf[C_ * C_];                 // Wv, tf32-RNA rounded

// ===========================================================================
// helpers
// ===========================================================================
__device__ __forceinline__ uint32_t smem_u32(const void* p) {
    uint32_t a;
    asm("{ .reg .u64 t; cvta.to.shared.u64 t, %1; cvt.u32.u64 %0, t; }"
        : "=r"(a) : "l"(p));
    return a;
}
__device__ __forceinline__ float tf32_rna(float f) {
    uint32_t u;
    asm("cvt.rna.tf32.f32 %0, %1;" : "=r"(u) : "f"(f));
    return __uint_as_float(u);
}
__device__ __forceinline__ float ex2f(float x) {
    float r;
    asm("ex2.approx.f32 %0, %1;" : "=f"(r) : "f"(x));
    return r;
}
// pack: lo = b, hi = a
__device__ __forceinline__ uint32_t bf16x2_pack(float hi, float lo) {
    uint32_t r;
    asm("cvt.rn.bf16x2.f32 %0, %1, %2;" : "=r"(r) : "f"(hi), "f"(lo));
    return r;
}
__device__ __forceinline__ void mma_tf32(float d[4], const float a[4],
                                         float b0, float b1) {
    asm volatile(
        "mma.sync.aligned.m16n8k8.row.col.f32.tf32.tf32.f32 "
        "{%0,%1,%2,%3}, {%4,%5,%6,%7}, {%8,%9}, {%0,%1,%2,%3};"
        : "+f"(d[0]), "+f"(d[1]), "+f"(d[2]), "+f"(d[3])
        : "r"(__float_as_uint(a[0])), "r"(__float_as_uint(a[1])),
          "r"(__float_as_uint(a[2])), "r"(__float_as_uint(a[3])),
          "r"(__float_as_uint(b0)),  "r"(__float_as_uint(b1)));
}
__device__ __forceinline__ void mma_bf16(float d[4], uint32_t a0, uint32_t a1,
                                         uint32_t a2, uint32_t a3,
                                         uint32_t b0, uint32_t b1) {
    asm volatile(
        "mma.sync.aligned.m16n8k16.row.col.f32.bf16.bf16.f32 "
        "{%0,%1,%2,%3}, {%4,%5,%6,%7}, {%8,%9}, {%0,%1,%2,%3};"
        : "+f"(d[0]), "+f"(d[1]), "+f"(d[2]), "+f"(d[3])
        : "r"(a0), "r"(a1), "r"(a2), "r"(a3), "r"(b0), "r"(b1));
}
#define CP_ASYNC16(dst, src) \
    asm volatile("cp.async.ca.shared.global [%0], [%1], 16;" \
        :: "r"(dst), "l"(src) : "memory")
#define CP_COMMIT() asm volatile("cp.async.commit_group;" ::: "memory")
#define BAR_PAIR(id) \
    asm volatile("bar.sync %0, %1;" :: "r"(id), "r"(64) : "memory")

// ===========================================================================
// W prepack: tf32-RNA round Wv into g_Wtf (avoids tf32 truncation bias)
// ===========================================================================
__global__ void wpack_kernel(const float* __restrict__ Wv) {
    const int i = blockIdx.x * 256 + threadIdx.x;
    g_Wtf[i] = tf32_rna(Wv[i]);
}

// ===========================================================================
// Fused Q+K projection (FFMA): stages x once, computes both.
//  Per-output accumulation order identical to the previous separate kernels
//  (c ascending within chunk, chunks ascending) -> bit-identical Q and K.
//  Q -> [B][32][T], scaled by log2e, tf32-rounded.
//  K -> [B][T][32] transposed, tf32-rounded.
// ===========================================================================
__global__ void __launch_bounds__(256) qkproj_kernel(
    const float* __restrict__ x,
    const float* __restrict__ Wq, const float* __restrict__ bq,
    const float* __restrict__ Wk, const float* __restrict__ bk,
    float* __restrict__ qout, float* __restrict__ kout)
{
    __shared__ float Ws[64 * 33];    // rows 0..31 = Wq, 32..63 = Wk
    __shared__ float xs[32 * 132];

    const int t0 = blockIdx.x * 128;
    const int b  = blockIdx.z;
    const int tid = threadIdx.x;
    const int oi = tid >> 5;          // 0..7
    const int ti = tid & 31;

    float acc[8][4];                  // a<4: Q (o = oi*4+a), a>=4: K
#pragma unroll
    for (int a = 0; a < 8; a++)
#pragma unroll
        for (int bb = 0; bb < 4; bb++) acc[a][bb] = 0.f;

    for (int k0 = 0; k0 < C_; k0 += 32) {
#pragma unroll
        for (int k = 0; k < 8; k++) {
            int idx = tid + 256 * k;
            int o = idx >> 5, c = idx & 31;     // o 0..63
            Ws[o * 33 + c] = (o < 32) ? Wq[o * C_ + k0 + c]
                                      : Wk[(o - 32) * C_ + k0 + c];
        }
#pragma unroll
        for (int k = 0; k < 4; k++) {
            int f = tid + 256 * k;
            int c = f >> 5, t4 = f & 31;
            const float4 v = *(const float4*)&x[((size_t)b * C_ + (k0 + c)) * T_ + t0 + t4 * 4];
            *(float4*)&xs[c * 132 + t4 * 4] = v;
        }
        __syncthreads();

#pragma unroll 8
        for (int c = 0; c < 32; c++) {
            float w[8], xv[4];
#pragma unroll
            for (int a = 0; a < 4; a++) {
                w[a]     = Ws[(oi * 4 + a) * 33 + c];
                w[4 + a] = Ws[(32 + oi * 4 + a) * 33 + c];
            }
#pragma unroll
            for (int bb = 0; bb < 4; bb++) xv[bb] = xs[c * 132 + ti + 32 * bb];
#pragma unroll
            for (int a = 0; a < 8; a++)
#pragma unroll
                for (int bb = 0; bb < 4; bb++) acc[a][bb] += w[a] * xv[bb];
        }
        __syncthreads();
    }

    // ---- Q epilogue: [32][T], scaled by log2e ----
#pragma unroll
    for (int a = 0; a < 4; a++) {
        const int o = oi * 4 + a;
        const float bo = bq[o];
#pragma unroll
        for (int bb = 0; bb < 4; bb++) {
            const int t = t0 + ti + 32 * bb;
            qout[((size_t)b * CQK_ + o) * T_ + t] =
                tf32_rna((acc[a][bb] + bo) * LOG2E_F);
        }
    }
    // ---- K epilogue: [T][32] transposed, float4 along o ----
    float bo[4];
#pragma unroll
    for (int a = 0; a < 4; a++) bo[a] = bk[oi * 4 + a];
#pragma unroll
    for (int bb = 0; bb < 4; bb++) {
        const int t = t0 + ti + 32 * bb;
        float4 v;
        v.x = tf32_rna(acc[4][bb] + bo[0]);
        v.y = tf32_rna(acc[5][bb] + bo[1]);
        v.z = tf32_rna(acc[6][bb] + bo[2]);
        v.w = tf32_rna(acc[7][bb] + bo[3]);
        *(float4*)&kout[((size_t)b * T_ + t) * 32 + oi * 4] = v;
    }
}

// ===========================================================================
// V projection (tf32 mma) — unchanged from R13 (56us, verified).
// ===========================================================================
#define XP_STRIDE 48
#define XP_BYTES (128 * XP_STRIDE * 4)      // 24576
#define WP_STRIDE 48
#define WP_BYTES (256 * WP_STRIDE * 4)      // 49152
#define VP_BUF (XP_BYTES + WP_BYTES)        // 73728
#define VP_SMEM (2 * VP_BUF)                // 147456

__global__ void __launch_bounds__(512, 1) vproj_mma_kernel(
    const float* __restrict__ x, const float* __restrict__ bv,
    __nv_bfloat16* __restrict__ V)
{
    extern __shared__ char smem[];
    const uint32_t sb = smem_u32(smem);
    const int tid = threadIdx.x;
    const int wid = tid >> 5, lid = tid & 31;
    const int g = lid >> 2, tig = lid & 3;
    const int rg = wid & 7;
    const int oh = wid >> 3;
    const int b = blockIdx.y;
    const int t0 = blockIdx.x * 128;

    const int xc = lid;
    const int xtq0 = wid, xtq1 = wid + 16;
    const float* xb = x + (size_t)b * C_ * T_ + t0;

    const int xs_a = ((rg * 16 + g) * XP_STRIDE + 4 * tig) * 4;
    const int ws_b = ((oh * 128 + g) * WP_STRIDE + 4 * tig) * 4;

    const uint32_t u0 = sb, u1 = sb + VP_BUF;
    const uint32_t sts0 = (uint32_t)((4 * xtq0) * XP_STRIDE + xc) * 4;
    const uint32_t sts1 = (uint32_t)((4 * xtq1) * XP_STRIDE + xc) * 4;

    float4 xr[2];
    float acc[16][4];
#pragma unroll
    for (int nb = 0; nb < 16; nb++)
#pragma unroll
        for (int e = 0; e < 4; e++) acc[nb][e] = 0.f;

    xr[0] = *(const float4*)(xb + (size_t)xc * T_ + 4 * xtq0);
    xr[1] = *(const float4*)(xb + (size_t)xc * T_ + 4 * xtq1);
    {
#pragma unroll
        for (int j = 0; j < 4; j++) {
            const int idx = tid + j * 512;
            const int o = idx >> 3, q = idx & 7;
            CP_ASYNC16(u0 + XP_BYTES + o * (WP_STRIDE * 4) + q * 16,
                       g_Wtf + (size_t)o * C_ + 4 * q);
        }
        CP_COMMIT();
    }

#pragma unroll
    for (int ch = 0; ch < 8; ch++) {
        const uint32_t ub = (ch & 1) ? u1 : u0;
        {
            const uint32_t a0 = ub + sts0;
            asm volatile("st.shared.f32 [%0], %1;"     :: "r"(a0), "f"(xr[0].x));
            asm volatile("st.shared.f32 [%0+192], %1;" :: "r"(a0), "f"(xr[0].y));
            asm volatile("st.shared.f32 [%0+384], %1;" :: "r"(a0), "f"(xr[0].z));
            asm volatile("st.shared.f32 [%0+576], %1;" :: "r"(a0), "f"(xr[0].w));
            const uint32_t a1 = ub + sts1;
            asm volatile("st.shared.f32 [%0], %1;"     :: "r"(a1), "f"(xr[1].x));
            asm volatile("st.shared.f32 [%0+192], %1;" :: "r"(a1), "f"(xr[1].y));
            asm volatile("st.shared.f32 [%0+384], %1;" :: "r"(a1), "f"(xr[1].z));
            asm volatile("st.shared.f32 [%0+576], %1;" :: "r"(a1), "f"(xr[1].w));
        }
        if (ch + 1 < 8) {
            const int cnext = (ch + 1) * 32 + xc;
            xr[0] = *(const float4*)(xb + (size_t)cnext * T_ + 4 * xtq0);
            xr[1] = *(const float4*)(xb + (size_t)cnext * T_ + 4 * xtq1);
            const uint32_t un = (ch & 1) ? u0 : u1;
#pragma unroll
            for (int j = 0; j < 4; j++) {
                const int idx = tid + j * 512;
                const int o = idx >> 3, q = idx & 7;
                CP_ASYNC16(un + XP_BYTES + o * (WP_STRIDE * 4) + q * 16,
                           g_Wtf + (size_t)o * C_ + (ch + 1) * 32 + 4 * q);
            }
            CP_COMMIT();
            asm volatile("cp.async.wait_group 1;" ::: "memory");
        } else {
            asm volatile("cp.async.wait_group 0;" ::: "memory");
        }
        __syncthreads();

        const char* sc = smem + (size_t)(ch & 1) * VP_BUF;
        const char* ax = sc + xs_a;
        const float4 fa0 = *(const float4*)(ax);
        const float4 fa1 = *(const float4*)(ax + 8 * XP_STRIDE * 4);
        const float4 fa2 = *(const float4*)(ax + 64);
        const float4 fa3 = *(const float4*)(ax + 8 * XP_STRIDE * 4 + 64);
        float aF[4][4];
        aF[0][0] = tf32_rna(fa0.x); aF[0][1] = tf32_rna(fa1.x);
        aF[0][2] = tf32_rna(fa2.x); aF[0][3] = tf32_rna(fa3.x);
        aF[1][0] = tf32_rna(fa0.y); aF[1][1] = tf32_rna(fa1.y);
        aF[1][2] = tf32_rna(fa2.y); aF[1][3] = tf32_rna(fa3.y);
        aF[2][0] = tf32_rna(fa0.z); aF[2][1] = tf32_rna(fa1.z);
        aF[2][2] = tf32_rna(fa2.z); aF[2][3] = tf32_rna(fa3.z);
        aF[3][0] = tf32_rna(fa0.w); aF[3][1] = tf32_rna(fa1.w);
        aF[3][2] = tf32_rna(fa2.w); aF[3][3] = tf32_rna(fa3.w);

        const char* bw = sc + XP_BYTES + ws_b;
#pragma unroll
        for (int nb = 0; nb < 16; nb++) {
            const float4 blo = *(const float4*)(bw + nb * 8 * (WP_STRIDE * 4));
            const float4 bhi = *(const float4*)(bw + nb * 8 * (WP_STRIDE * 4) + 64);
            mma_tf32(acc[nb], aF[0], blo.x, bhi.x);
            mma_tf32(acc[nb], aF[1], blo.y, bhi.y);
            mma_tf32(acc[nb], aF[2], blo.z, bhi.z);
            mma_tf32(acc[nb], aF[3], blo.w, bhi.w);
        }
        __syncthreads();
    }

    float* Osm = (float*)smem;
    __nv_bfloat16* Vb = V + (size_t)b * C_ * T_ + t0;
    for (int r = 0; r < 4; r++) {
        __syncthreads();
        if ((r >> 1) == oh) {
            const int nbb = (r & 1) * 8;
            const int tl = rg * 16 + g;
#pragma unroll
            for (int nbl = 0; nbl < 8; nbl++) {
                const int nb = nbb + nbl;
                const int o2 = nbl * 8 + 2 * tig;
                Osm[(o2 + 0) * 132 + tl]     = acc[nb][0];
                Osm[(o2 + 1) * 132 + tl]     = acc[nb][1];
                Osm[(o2 + 0) * 132 + tl + 8] = acc[nb][2];
                Osm[(o2 + 1) * 132 + tl + 8] = acc[nb][3];
            }
        }
        __syncthreads();
#pragma unroll
        for (int k = 0; k < 4; k++) {
            const int idx = tid + k * 512;
            const int op = idx >> 5, tq = idx & 31;
            float4 v = *(const float4*)&Osm[op * 132 + tq * 4];
            const float bo = __ldg(&bv[r * 64 + op]);
            v.x += bo; v.y += bo; v.z += bo; v.w += bo;
            uint2 st;
            st.x = bf16x2_pack(v.y, v.x);
            st.y = bf16x2_pack(v.w, v.z);
            *(uint2*)&Vb[(size_t)(r * 64 + op) * T_ + tq * 4] = st;
        }
    }
}

// ===========================================================================
// Attention v8 (R13/R11 winner, reverted verbatim): 512 threads, 16 warps.
// ===========================================================================
#define KT_STRIDE 48
#define KT_BYTES (32 * KT_STRIDE * 4)       // 6144
#define VS_STRIDE_B 64
#define VS_BYTES (256 * VS_STRIDE_B)        // 16384
#define STAGE_BYTES (KT_BYTES + VS_BYTES)   // 22528
#define PS_OFF  (3 * STAGE_BYTES)           // 67584
#define PS_STRIDE_B 80
#define PS_BYTES (128 * PS_STRIDE_B)        // 10240
#define LS_OFF  (PS_OFF + PS_BYTES)         // 77824
#define SMEM_BYTES (LS_OFF + 1024)          // 78848

#define MMA1_4(sdrow, aq, lo, hi) \
    mma_tf32(sdrow, aq[0], lo.x, hi.x); \
    mma_tf32(sdrow, aq[1], lo.y, hi.y); \
    mma_tf32(sdrow, aq[2], lo.z, hi.z); \
    mma_tf32(sdrow, aq[3], lo.w, hi.w);

__global__ void __launch_bounds__(512, 1) attn_mma_kernel(
    const float* __restrict__ x, float* __restrict__ out)
{
    extern __shared__ char smem[];
    const uint32_t sb = smem_u32(smem);

    const int tid = threadIdx.x;
    const int wid = tid >> 5, lid = tid & 31;
    const int g   = lid >> 2, tig = lid & 3;
    const int rg  = wid & 7;
    const int ch  = wid >> 3;
    const int b  = blockIdx.y;
    const int t0 = blockIdx.x * 128;
    const int prow = rg * 16;

    const int krow = (tid & 255) >> 3, chn8 = tid & 7;
    const uint32_t k_dst = (uint32_t)(krow * (KT_STRIDE * 4) + chn8 * 16);
    const float* kg = &g_K[(size_t)b * T_ * CQK_] + (size_t)krow * CQK_ + chn8 * 4;
    const int vrow = tid >> 1, vhalf = tid & 1;
    const uint32_t v_dst = (uint32_t)(KT_BYTES + vrow * VS_STRIDE_B + vhalf * 32);
    const __nv_bfloat16* vg = &g_V[(size_t)b * C_ * T_] + (size_t)vrow * T_ + vhalf * 16;

    const int kf_off = ((ch * 16 + g) * KT_STRIDE + 4 * tig) * 4;
    const int vf_off = KT_BYTES + (ch * 128 + g) * VS_STRIDE_B + 16 * tig;

    char* PsB = smem + PS_OFF;
    const uint32_t ps_w = (uint32_t)((prow + g) * PS_STRIDE_B + 32 * ch + 4 * tig);
    const char* ps_r = PsB + (prow + g) * PS_STRIDE_B + 16 * tig;

    const char* s0 = smem;
    const char* s1 = smem + STAGE_BYTES;
    const char* s2 = smem + 2 * STAGE_BYTES;
    uint32_t u0 = sb, u1 = sb + STAGE_BYTES, u2 = sb + 2 * STAGE_BYTES;

    auto stage_to = [&](uint32_t base) {
        if (tid < 256) CP_ASYNC16(base + k_dst, kg);
        kg += 32 * CQK_;
        CP_ASYNC16(base + v_dst,      vg);
        CP_ASYNC16(base + v_dst + 16, vg + 8);
        vg += 32;
        CP_COMMIT();
    };

    stage_to(u0);
    stage_to(u1);

    float aQ[4][4];
    {
        const float* qb = &g_Q[(size_t)b * CQK_ * T_];
        const int rowb = t0 + prow;
#pragma unroll
        for (int kb = 0; kb < 4; kb++) {
            aQ[kb][0] = qb[(4 * tig + kb) * T_      + rowb + g];
            aQ[kb][1] = qb[(4 * tig + kb) * T_      + rowb + g + 8];
            aQ[kb][2] = qb[(4 * tig + 16 + kb) * T_ + rowb + g];
            aQ[kb][3] = qb[(4 * tig + 16 + kb) * T_ + rowb + g + 8];
        }
    }

    float acc[16][4];
#pragma unroll
    for (int nb = 0; nb < 16; nb++)
#pragma unroll
        for (int e = 0; e < 4; e++) acc[nb][e] = 0.f;
    float lsum0 = 0.f, lsum1 = 0.f;

    const int NSTEP = T_ / 32;
    const int barid = rg + 1;

    for (int it = 0; it < NSTEP; it++) {
        if (it + 1 < NSTEP) {
            asm volatile("cp.async.wait_group 1;" ::: "memory");
        } else {
            asm volatile("cp.async.wait_group 0;" ::: "memory");
        }
        __syncthreads();
        if (it + 2 < NSTEP) stage_to(u2);

        const char* Kw = s0 + kf_off;
        float sd[2][4];
#pragma unroll
        for (int nbl = 0; nbl < 2; nbl++)
#pragma unroll
            for (int e = 0; e < 4; e++) sd[nbl][e] = 0.f;
        {
            const float4 lo0 = *(const float4*)(Kw);
            const float4 hi0 = *(const float4*)(Kw + 64);
            const float4 lo1 = *(const float4*)(Kw + 8 * KT_STRIDE * 4);
            const float4 hi1 = *(const float4*)(Kw + 8 * KT_STRIDE * 4 + 64);
            MMA1_4(sd[0], aQ, lo0, hi0);
            MMA1_4(sd[1], aQ, lo1, hi1);
        }

#pragma unroll
        for (int nbl = 0; nbl < 2; nbl++) {
            const float p0 = ex2f(sd[nbl][0]);
            const float p1 = ex2f(sd[nbl][1]);
            const float p2 = ex2f(sd[nbl][2]);
            const float p3 = ex2f(sd[nbl][3]);
            const uint32_t pk01 = bf16x2_pack(p1, p0);
            const uint32_t pk23 = bf16x2_pack(p3, p2);
            lsum0 += __uint_as_float(pk01 << 16)
                   + __uint_as_float(pk01 & 0xFFFF0000u);
            lsum1 += __uint_as_float(pk23 << 16)
                   + __uint_as_float(pk23 & 0xFFFF0000u);
            const uint32_t woff = ps_w + (uint32_t)(nbl * 16);
            *(uint32_t*)(PsB + woff)                   = pk01;
            *(uint32_t*)(PsB + woff + 8 * PS_STRIDE_B) = pk23;
        }
        BAR_PAIR(barid);

        const uint4 pA0 = *(const uint4*)(ps_r);
        const uint4 pA1 = *(const uint4*)(ps_r + 8 * PS_STRIDE_B);

        const char* Vw = s0 + vf_off;
#pragma unroll
        for (int nb = 0; nb < 16; nb++) {
            const uint4 vq = *(const uint4*)(Vw + nb * 8 * VS_STRIDE_B);
            mma_bf16(acc[nb], pA0.x, pA1.x, pA0.y, pA1.y, vq.x, vq.y);
            mma_bf16(acc[nb], pA0.z, pA1.z, pA0.w, pA1.w, vq.z, vq.w);
        }

        const char* stmp = s0; s0 = s1; s1 = s2; s2 = stmp;
        const uint32_t utmp = u0; u0 = u1; u1 = u2; u2 = utmp;
    }

    lsum0 += __shfl_xor_sync(0xffffffffu, lsum0, 1);
    lsum0 += __shfl_xor_sync(0xffffffffu, lsum0, 2);
    lsum1 += __shfl_xor_sync(0xffffffffu, lsum1, 1);
    lsum1 += __shfl_xor_sync(0xffffffffu, lsum1, 2);
    float* LS = (float*)(smem + LS_OFF);
    __syncthreads();
    LS[(prow + g) * 2 + ch]     = lsum0;
    LS[(prow + 8 + g) * 2 + ch] = lsum1;
    __syncthreads();
    const float inv0 = 1.0f / (LS[(prow + g) * 2]     + LS[(prow + g) * 2 + 1]);
    const float inv1 = 1.0f / (LS[(prow + 8 + g) * 2] + LS[(prow + 8 + g) * 2 + 1]);

    float* Osm = (float*)smem;
    const int tl = prow + g;
    for (int cc = 0; cc < 8; cc++) {
        __syncthreads();
        if ((cc >> 2) == ch) {
#pragma unroll
            for (int nbl = 0; nbl < 4; nbl++) {
                const int nb = (cc & 3) * 4 + nbl;
                const int c0 = nbl * 8 + 2 * tig;
                Osm[(c0 + 0) * 132 + tl]     = acc[nb][0] * inv0;
                Osm[(c0 + 1) * 132 + tl]     = acc[nb][1] * inv0;
                Osm[(c0 + 0) * 132 + tl + 8] = acc[nb][2] * inv1;
                Osm[(c0 + 1) * 132 + tl + 8] = acc[nb][3] * inv1;
            }
        }
        __syncthreads();
#pragma unroll
        for (int k = 0; k < 2; k++) {
            const int i = tid + k * 512;
            const int c = i >> 5;
            const int t4 = i & 31;
            float4 v = *(const float4*)&Osm[c * 132 + t4 * 4];
            const size_t gi = ((size_t)b * C_ + cc * 32 + c) * T_ + t0 + t4 * 4;
            const float4 xv = *(const float4*)&x[gi];
            v.x += xv.x; v.y += xv.y; v.z += xv.z; v.w += xv.w;
            *(float4*)&out[gi] = v;
        }
    }
}

// ===========================================================================
extern "C" void kernel_launch(void* const* d_in, const int* in_sizes, int n_in,
                              void* d_out, int out_size)
{
    const float* x  = (const float*)d_in[0];
    const float* Wq = (const float*)d_in[1];
    const float* bq = (const float*)d_in[2];
    const float* Wk = (const float*)d_in[3];
    const float* bk = (const float*)d_in[4];
    const float* Wv = (const float*)d_in[5];
    const float* bv = (const float*)d_in[6];
    float* out = (float*)d_out;

    void *qp, *kp, *vp;
    cudaGetSymbolAddress(&qp, g_Q);
    cudaGetSymbolAddress(&kp, g_K);
    cudaGetSymbolAddress(&vp, g_V);

    cudaFuncSetAttribute(attn_mma_kernel,
                         cudaFuncAttributeMaxDynamicSharedMemorySize, SMEM_BYTES);
    cudaFuncSetAttribute(vproj_mma_kernel,
                         cudaFuncAttributeMaxDynamicSharedMemorySize, VP_SMEM);

    wpack_kernel<<<C_ * C_ / 256, 256>>>(Wv);
    qkproj_kernel<<<dim3(T_ / 128, 1, B_), 256>>>(x, Wq, bq, Wk, bk,
                                                  (float*)qp, (float*)kp);
    vproj_mma_kernel<<<dim3(T_ / 128, B_), 512, VP_SMEM>>>(
        x, bv, (__nv_bfloat16*)vp);
    attn_mma_kernel<<<dim3(T_ / 128, B_), 512, SMEM_BYTES>>>(x, out);
}

// round 16
// speedup vs baseline: 1.1143x; 1.0484x over previous
#include <cuda_runtime.h>
#include <cuda_bf16.h>
#include <math.h>
#include <stdint.h>

#define B_  16
#define C_  256
#define T_  2048
#define CQK_ 32
#define LOG2E_F 1.4426950408889634f

// Scratch (allocation-free rule: __device__ globals)
__device__ float g_Q[B_ * CQK_ * T_];            // [B][32][T] tf32, pre-scaled log2e
__device__ float g_K[B_ * T_ * CQK_];            // [B][T][32] transposed, tf32
__device__ __nv_bfloat16 g_V[B_ * C_ * T_];      // [B][256][T] bf16
__device__ float g_Wtf[C_ * C_];                 // Wv, tf32-RNA rounded

// ===========================================================================
// helpers
// ===========================================================================
__device__ __forceinline__ uint32_t smem_u32(const void* p) {
    uint32_t a;
    asm("{ .reg .u64 t; cvta.to.shared.u64 t, %1; cvt.u32.u64 %0, t; }"
        : "=r"(a) : "l"(p));
    return a;
}
__device__ __forceinline__ float tf32_rna(float f) {
    uint32_t u;
    asm("cvt.rna.tf32.f32 %0, %1;" : "=r"(u) : "f"(f));
    return __uint_as_float(u);
}
__device__ __forceinline__ float ex2f(float x) {
    float r;
    asm("ex2.approx.f32 %0, %1;" : "=f"(r) : "f"(x));
    return r;
}
// pack: lo = b, hi = a
__device__ __forceinline__ uint32_t bf16x2_pack(float hi, float lo) {
    uint32_t r;
    asm("cvt.rn.bf16x2.f32 %0, %1, %2;" : "=r"(r) : "f"(hi), "f"(lo));
    return r;
}
__device__ __forceinline__ void mma_tf32(float d[4], const float a[4],
                                         float b0, float b1) {
    asm volatile(
        "mma.sync.aligned.m16n8k8.row.col.f32.tf32.tf32.f32 "
        "{%0,%1,%2,%3}, {%4,%5,%6,%7}, {%8,%9}, {%0,%1,%2,%3};"
        : "+f"(d[0]), "+f"(d[1]), "+f"(d[2]), "+f"(d[3])
        : "r"(__float_as_uint(a[0])), "r"(__float_as_uint(a[1])),
          "r"(__float_as_uint(a[2])), "r"(__float_as_uint(a[3])),
          "r"(__float_as_uint(b0)),  "r"(__float_as_uint(b1)));
}
__device__ __forceinline__ void mma_bf16(float d[4], uint32_t a0, uint32_t a1,
                                         uint32_t a2, uint32_t a3,
                                         uint32_t b0, uint32_t b1) {
    asm volatile(
        "mma.sync.aligned.m16n8k16.row.col.f32.bf16.bf16.f32 "
        "{%0,%1,%2,%3}, {%4,%5,%6,%7}, {%8,%9}, {%0,%1,%2,%3};"
        : "+f"(d[0]), "+f"(d[1]), "+f"(d[2]), "+f"(d[3])
        : "r"(a0), "r"(a1), "r"(a2), "r"(a3), "r"(b0), "r"(b1));
}
#define CP_ASYNC16(dst, src) \
    asm volatile("cp.async.ca.shared.global [%0], [%1], 16;" \
        :: "r"(dst), "l"(src) : "memory")
#define CP_COMMIT() asm volatile("cp.async.commit_group;" ::: "memory")
#define BAR_PAIR(id) \
    asm volatile("bar.sync %0, %1;" :: "r"(id), "r"(64) : "memory")

// ===========================================================================
// W prepack: tf32-RNA round Wv into g_Wtf (avoids tf32 truncation bias)
// ===========================================================================
__global__ void wpack_kernel(const float* __restrict__ Wv) {
    const int i = blockIdx.x * 256 + threadIdx.x;
    g_Wtf[i] = tf32_rna(Wv[i]);
}

// ===========================================================================
// Fused Q+K projection (FFMA) — unchanged from R15 (bit-identical Q/K).
// ===========================================================================
__global__ void __launch_bounds__(256) qkproj_kernel(
    const float* __restrict__ x,
    const float* __restrict__ Wq, const float* __restrict__ bq,
    const float* __restrict__ Wk, const float* __restrict__ bk,
    float* __restrict__ qout, float* __restrict__ kout)
{
    __shared__ float Ws[64 * 33];
    __shared__ float xs[32 * 132];

    const int t0 = blockIdx.x * 128;
    const int b  = blockIdx.z;
    const int tid = threadIdx.x;
    const int oi = tid >> 5;
    const int ti = tid & 31;

    float acc[8][4];
#pragma unroll
    for (int a = 0; a < 8; a++)
#pragma unroll
        for (int bb = 0; bb < 4; bb++) acc[a][bb] = 0.f;

    for (int k0 = 0; k0 < C_; k0 += 32) {
#pragma unroll
        for (int k = 0; k < 8; k++) {
            int idx = tid + 256 * k;
            int o = idx >> 5, c = idx & 31;
            Ws[o * 33 + c] = (o < 32) ? Wq[o * C_ + k0 + c]
                                      : Wk[(o - 32) * C_ + k0 + c];
        }
#pragma unroll
        for (int k = 0; k < 4; k++) {
            int f = tid + 256 * k;
            int c = f >> 5, t4 = f & 31;
            const float4 v = *(const float4*)&x[((size_t)b * C_ + (k0 + c)) * T_ + t0 + t4 * 4];
            *(float4*)&xs[c * 132 + t4 * 4] = v;
        }
        __syncthreads();

#pragma unroll 8
        for (int c = 0; c < 32; c++) {
            float w[8], xv[4];
#pragma unroll
            for (int a = 0; a < 4; a++) {
                w[a]     = Ws[(oi * 4 + a) * 33 + c];
                w[4 + a] = Ws[(32 + oi * 4 + a) * 33 + c];
            }
#pragma unroll
            for (int bb = 0; bb < 4; bb++) xv[bb] = xs[c * 132 + ti + 32 * bb];
#pragma unroll
            for (int a = 0; a < 8; a++)
#pragma unroll
                for (int bb = 0; bb < 4; bb++) acc[a][bb] += w[a] * xv[bb];
        }
        __syncthreads();
    }

#pragma unroll
    for (int a = 0; a < 4; a++) {
        const int o = oi * 4 + a;
        const float bo = bq[o];
#pragma unroll
        for (int bb = 0; bb < 4; bb++) {
            const int t = t0 + ti + 32 * bb;
            qout[((size_t)b * CQK_ + o) * T_ + t] =
                tf32_rna((acc[a][bb] + bo) * LOG2E_F);
        }
    }
    float bo[4];
#pragma unroll
    for (int a = 0; a < 4; a++) bo[a] = bk[oi * 4 + a];
#pragma unroll
    for (int bb = 0; bb < 4; bb++) {
        const int t = t0 + ti + 32 * bb;
        float4 v;
        v.x = tf32_rna(acc[4][bb] + bo[0]);
        v.y = tf32_rna(acc[5][bb] + bo[1]);
        v.z = tf32_rna(acc[6][bb] + bo[2]);
        v.w = tf32_rna(acc[7][bb] + bo[3]);
        *(float4*)&kout[((size_t)b * T_ + t) * 32 + oi * 4] = v;
    }
}

// ===========================================================================
// V projection (tf32 mma) — unchanged from R13 (56us, verified).
// ===========================================================================
#define XP_STRIDE 48
#define XP_BYTES (128 * XP_STRIDE * 4)      // 24576
#define WP_STRIDE 48
#define WP_BYTES (256 * WP_STRIDE * 4)      // 49152
#define VP_BUF (XP_BYTES + WP_BYTES)        // 73728
#define VP_SMEM (2 * VP_BUF)                // 147456

__global__ void __launch_bounds__(512, 1) vproj_mma_kernel(
    const float* __restrict__ x, const float* __restrict__ bv,
    __nv_bfloat16* __restrict__ V)
{
    extern __shared__ char smem[];
    const uint32_t sb = smem_u32(smem);
    const int tid = threadIdx.x;
    const int wid = tid >> 5, lid = tid & 31;
    const int g = lid >> 2, tig = lid & 3;
    const int rg = wid & 7;
    const int oh = wid >> 3;
    const int b = blockIdx.y;
    const int t0 = blockIdx.x * 128;

    const int xc = lid;
    const int xtq0 = wid, xtq1 = wid + 16;
    const float* xb = x + (size_t)b * C_ * T_ + t0;

    const int xs_a = ((rg * 16 + g) * XP_STRIDE + 4 * tig) * 4;
    const int ws_b = ((oh * 128 + g) * WP_STRIDE + 4 * tig) * 4;

    const uint32_t u0 = sb, u1 = sb + VP_BUF;
    const uint32_t sts0 = (uint32_t)((4 * xtq0) * XP_STRIDE + xc) * 4;
    const uint32_t sts1 = (uint32_t)((4 * xtq1) * XP_STRIDE + xc) * 4;

    float4 xr[2];
    float acc[16][4];
#pragma unroll
    for (int nb = 0; nb < 16; nb++)
#pragma unroll
        for (int e = 0; e < 4; e++) acc[nb][e] = 0.f;

    xr[0] = *(const float4*)(xb + (size_t)xc * T_ + 4 * xtq0);
    xr[1] = *(const float4*)(xb + (size_t)xc * T_ + 4 * xtq1);
    {
#pragma unroll
        for (int j = 0; j < 4; j++) {
            const int idx = tid + j * 512;
            const int o = idx >> 3, q = idx & 7;
            CP_ASYNC16(u0 + XP_BYTES + o * (WP_STRIDE * 4) + q * 16,
                       g_Wtf + (size_t)o * C_ + 4 * q);
        }
        CP_COMMIT();
    }

#pragma unroll
    for (int ch = 0; ch < 8; ch++) {
        const uint32_t ub = (ch & 1) ? u1 : u0;
        {
            const uint32_t a0 = ub + sts0;
            asm volatile("st.shared.f32 [%0], %1;"     :: "r"(a0), "f"(xr[0].x));
            asm volatile("st.shared.f32 [%0+192], %1;" :: "r"(a0), "f"(xr[0].y));
            asm volatile("st.shared.f32 [%0+384], %1;" :: "r"(a0), "f"(xr[0].z));
            asm volatile("st.shared.f32 [%0+576], %1;" :: "r"(a0), "f"(xr[0].w));
            const uint32_t a1 = ub + sts1;
            asm volatile("st.shared.f32 [%0], %1;"     :: "r"(a1), "f"(xr[1].x));
            asm volatile("st.shared.f32 [%0+192], %1;" :: "r"(a1), "f"(xr[1].y));
            asm volatile("st.shared.f32 [%0+384], %1;" :: "r"(a1), "f"(xr[1].z));
            asm volatile("st.shared.f32 [%0+576], %1;" :: "r"(a1), "f"(xr[1].w));
        }
        if (ch + 1 < 8) {
            const int cnext = (ch + 1) * 32 + xc;
            xr[0] = *(const float4*)(xb + (size_t)cnext * T_ + 4 * xtq0);
            xr[1] = *(const float4*)(xb + (size_t)cnext * T_ + 4 * xtq1);
            const uint32_t un = (ch & 1) ? u0 : u1;
#pragma unroll
            for (int j = 0; j < 4; j++) {
                const int idx = tid + j * 512;
                const int o = idx >> 3, q = idx & 7;
                CP_ASYNC16(un + XP_BYTES + o * (WP_STRIDE * 4) + q * 16,
                           g_Wtf + (size_t)o * C_ + (ch + 1) * 32 + 4 * q);
            }
            CP_COMMIT();
            asm volatile("cp.async.wait_group 1;" ::: "memory");
        } else {
            asm volatile("cp.async.wait_group 0;" ::: "memory");
        }
        __syncthreads();

        const char* sc = smem + (size_t)(ch & 1) * VP_BUF;
        const char* ax = sc + xs_a;
        const float4 fa0 = *(const float4*)(ax);
        const float4 fa1 = *(const float4*)(ax + 8 * XP_STRIDE * 4);
        const float4 fa2 = *(const float4*)(ax + 64);
        const float4 fa3 = *(const float4*)(ax + 8 * XP_STRIDE * 4 + 64);
        float aF[4][4];
        aF[0][0] = tf32_rna(fa0.x); aF[0][1] = tf32_rna(fa1.x);
        aF[0][2] = tf32_rna(fa2.x); aF[0][3] = tf32_rna(fa3.x);
        aF[1][0] = tf32_rna(fa0.y); aF[1][1] = tf32_rna(fa1.y);
        aF[1][2] = tf32_rna(fa2.y); aF[1][3] = tf32_rna(fa3.y);
        aF[2][0] = tf32_rna(fa0.z); aF[2][1] = tf32_rna(fa1.z);
        aF[2][2] = tf32_rna(fa2.z); aF[2][3] = tf32_rna(fa3.z);
        aF[3][0] = tf32_rna(fa0.w); aF[3][1] = tf32_rna(fa1.w);
        aF[3][2] = tf32_rna(fa2.w); aF[3][3] = tf32_rna(fa3.w);

        const char* bw = sc + XP_BYTES + ws_b;
#pragma unroll
        for (int nb = 0; nb < 16; nb++) {
            const float4 blo = *(const float4*)(bw + nb * 8 * (WP_STRIDE * 4));
            const float4 bhi = *(const float4*)(bw + nb * 8 * (WP_STRIDE * 4) + 64);
            mma_tf32(acc[nb], aF[0], blo.x, bhi.x);
            mma_tf32(acc[nb], aF[1], blo.y, bhi.y);
            mma_tf32(acc[nb], aF[2], blo.z, bhi.z);
            mma_tf32(acc[nb], aF[3], blo.w, bhi.w);
        }
        __syncthreads();
    }

    float* Osm = (float*)smem;
    __nv_bfloat16* Vb = V + (size_t)b * C_ * T_ + t0;
    for (int r = 0; r < 4; r++) {
        __syncthreads();
        if ((r >> 1) == oh) {
            const int nbb = (r & 1) * 8;
            const int tl = rg * 16 + g;
#pragma unroll
            for (int nbl = 0; nbl < 8; nbl++) {
                const int nb = nbb + nbl;
                const int o2 = nbl * 8 + 2 * tig;
                Osm[(o2 + 0) * 132 + tl]     = acc[nb][0];
                Osm[(o2 + 1) * 132 + tl]     = acc[nb][1];
                Osm[(o2 + 0) * 132 + tl + 8] = acc[nb][2];
                Osm[(o2 + 1) * 132 + tl + 8] = acc[nb][3];
            }
        }
        __syncthreads();
#pragma unroll
        for (int k = 0; k < 4; k++) {
            const int idx = tid + k * 512;
            const int op = idx >> 5, tq = idx & 31;
            float4 v = *(const float4*)&Osm[op * 132 + tq * 4];
            const float bo = __ldg(&bv[r * 64 + op]);
            v.x += bo; v.y += bo; v.z += bo; v.w += bo;
            uint2 st;
            st.x = bf16x2_pack(v.y, v.x);
            st.y = bf16x2_pack(v.w, v.z);
            *(uint2*)&Vb[(size_t)(r * 64 + op) * T_ + tq * 4] = st;
        }
    }
}

// ===========================================================================
// Attention v10: s-tile 64 (32 epochs instead of 64).
//  512 threads, 16 warps = 8 rowgroups(16 rows) x 2 s/col-halves.
//  K tile 64x192B, V tile 256x192B (both LDS.128 bank-clean), P = two 80B
//  tiles (R11's proven layout per 32-s half). MMA order s-ascending ->
//  bit-identical numerics to R15.
// ===========================================================================
#define KT_STRIDE 48
#define KT_BYTES (64 * KT_STRIDE * 4)       // 12288
#define VS_STRIDE_B 192                     // 128 used + 64 pad (== 64 mod 128)
#define VS_BYTES (256 * VS_STRIDE_B)        // 49152
#define STAGE_BYTES (KT_BYTES + VS_BYTES)   // 61440
#define PS_OFF  (3 * STAGE_BYTES)           // 184320
#define PS_STRIDE_B 80
#define PS_BYTES (128 * PS_STRIDE_B)        // 10240 per tile, 2 tiles
#define LS_OFF  (PS_OFF + 2 * PS_BYTES)     // 204800
#define SMEM_BYTES (LS_OFF + 1024)          // 205824

#define MMA1_4(sdrow, aq, lo, hi) \
    mma_tf32(sdrow, aq[0], lo.x, hi.x); \
    mma_tf32(sdrow, aq[1], lo.y, hi.y); \
    mma_tf32(sdrow, aq[2], lo.z, hi.z); \
    mma_tf32(sdrow, aq[3], lo.w, hi.w);

__global__ void __launch_bounds__(512, 1) attn_mma_kernel(
    const float* __restrict__ x, float* __restrict__ out)
{
    extern __shared__ char smem[];
    const uint32_t sb = smem_u32(smem);

    const int tid = threadIdx.x;
    const int wid = tid >> 5, lid = tid & 31;
    const int g   = lid >> 2, tig = lid & 3;
    const int rg  = wid & 7;
    const int ch  = wid >> 3;
    const int b  = blockIdx.y;
    const int t0 = blockIdx.x * 128;
    const int prow = rg * 16;

    // ---- staging: K 64 rows x 32c (512 chunks, 1/thread) ----
    const int krow = tid >> 3, chn8 = tid & 7;
    const uint32_t k_dst = (uint32_t)(krow * (KT_STRIDE * 4) + chn8 * 16);
    const float* kg = &g_K[(size_t)b * T_ * CQK_] + (size_t)krow * CQK_ + chn8 * 4;
    // V: 256 rows x 64 s bf16 (2048 chunks, 4/thread)
    const __nv_bfloat16* vg = &g_V[(size_t)b * C_ * T_];

    // fragment byte offsets
    const int kf_off = ((ch * 32 + g) * KT_STRIDE + 4 * tig) * 4;
    const int vf_off = KT_BYTES + (ch * 128 + g) * VS_STRIDE_B + 16 * tig;

    // P tiles: tile h (s-half) at PS_OFF + h*PS_BYTES, R11 layout each.
    char* PsW = smem + PS_OFF + ch * PS_BYTES;   // this warp writes tile ch
    const uint32_t ps_w = (uint32_t)((prow + g) * PS_STRIDE_B + 4 * tig);
    const int ps_roff = (prow + g) * PS_STRIDE_B + 16 * tig;
    const char* pr0 = smem + PS_OFF + ps_roff;
    const char* pr1 = smem + PS_OFF + PS_BYTES + ps_roff;

    const char* s0 = smem;
    const char* s1 = smem + STAGE_BYTES;
    const char* s2 = smem + 2 * STAGE_BYTES;
    uint32_t u0 = sb, u1 = sb + STAGE_BYTES, u2 = sb + 2 * STAGE_BYTES;

    int vstep = 0;
    auto stage_to = [&](uint32_t base) {
        CP_ASYNC16(base + k_dst, kg);
        kg += 64 * CQK_;
#pragma unroll
        for (int k = 0; k < 4; k++) {
            const int idx = tid + k * 512;
            const int row = idx >> 3, chn = idx & 7;
            CP_ASYNC16(base + KT_BYTES + row * VS_STRIDE_B + chn * 16,
                       vg + (size_t)row * T_ + vstep + chn * 8);
        }
        vstep += 64;
        CP_COMMIT();
    };

    stage_to(u0);
    stage_to(u1);

    float aQ[4][4];
    {
        const float* qb = &g_Q[(size_t)b * CQK_ * T_];
        const int rowb = t0 + prow;
#pragma unroll
        for (int kb = 0; kb < 4; kb++) {
            aQ[kb][0] = qb[(4 * tig + kb) * T_      + rowb + g];
            aQ[kb][1] = qb[(4 * tig + kb) * T_      + rowb + g + 8];
            aQ[kb][2] = qb[(4 * tig + 16 + kb) * T_ + rowb + g];
            aQ[kb][3] = qb[(4 * tig + 16 + kb) * T_ + rowb + g + 8];
        }
    }

    float acc[16][4];
#pragma unroll
    for (int nb = 0; nb < 16; nb++)
#pragma unroll
        for (int e = 0; e < 4; e++) acc[nb][e] = 0.f;
    float lsum0 = 0.f, lsum1 = 0.f;

    const int NSTEP = T_ / 64;   // 32
    const int barid = rg + 1;

    for (int it = 0; it < NSTEP; it++) {
        if (it + 1 < NSTEP) {
            asm volatile("cp.async.wait_group 1;" ::: "memory");
        } else {
            asm volatile("cp.async.wait_group 0;" ::: "memory");
        }
        __syncthreads();
        if (it + 2 < NSTEP) stage_to(u2);

        // ---- MMA1 (tf32): this warp's S quarter [16 t x 32 s] ----
        const char* Kw = s0 + kf_off;
        float sd[4][4];
#pragma unroll
        for (int nbl = 0; nbl < 4; nbl++)
#pragma unroll
            for (int e = 0; e < 4; e++) sd[nbl][e] = 0.f;
#pragma unroll
        for (int nbl = 0; nbl < 4; nbl++) {
            const float4 lo = *(const float4*)(Kw + nbl * 8 * (KT_STRIDE * 4));
            const float4 hi = *(const float4*)(Kw + nbl * 8 * (KT_STRIDE * 4) + 64);
            MMA1_4(sd[nbl], aQ, lo, hi);
        }

        // ---- P = 2^S -> bf16 into tile ch; lsum from bf16-rounded ----
#pragma unroll
        for (int nbl = 0; nbl < 4; nbl++) {
            const float p0 = ex2f(sd[nbl][0]);
            const float p1 = ex2f(sd[nbl][1]);
            const float p2 = ex2f(sd[nbl][2]);
            const float p3 = ex2f(sd[nbl][3]);
            const uint32_t pk01 = bf16x2_pack(p1, p0);
            const uint32_t pk23 = bf16x2_pack(p3, p2);
            lsum0 += __uint_as_float(pk01 << 16)
                   + __uint_as_float(pk01 & 0xFFFF0000u);
            lsum1 += __uint_as_float(pk23 << 16)
                   + __uint_as_float(pk23 & 0xFFFF0000u);
            const uint32_t woff = ps_w + (uint32_t)(nbl * 16);
            *(uint32_t*)(PsW + woff)                   = pk01;
            *(uint32_t*)(PsW + woff + 8 * PS_STRIDE_B) = pk23;
        }
        BAR_PAIR(barid);   // both warps of this rowgroup: P rows complete

        // ---- P A-frags: 2 tiles x 2 row-halves ----
        const uint4 pA00 = *(const uint4*)(pr0);
        const uint4 pA01 = *(const uint4*)(pr0 + 8 * PS_STRIDE_B);
        const uint4 pA10 = *(const uint4*)(pr1);
        const uint4 pA11 = *(const uint4*)(pr1 + 8 * PS_STRIDE_B);

        // ---- MMA2 (bf16): O[16x128] += P V^T, s-ascending order ----
        const char* Vw = s0 + vf_off;
#pragma unroll
        for (int nb = 0; nb < 16; nb++) {
            const uint4 va = *(const uint4*)(Vw + nb * 8 * VS_STRIDE_B);
            const uint4 vb = *(const uint4*)(Vw + nb * 8 * VS_STRIDE_B + 64);
            mma_bf16(acc[nb], pA00.x, pA01.x, pA00.y, pA01.y, va.x, va.y);
            mma_bf16(acc[nb], pA00.z, pA01.z, pA00.w, pA01.w, va.z, va.w);
            mma_bf16(acc[nb], pA10.x, pA11.x, pA10.y, pA11.y, vb.x, vb.y);
            mma_bf16(acc[nb], pA10.z, pA11.z, pA10.w, pA11.w, vb.z, vb.w);
        }

        const char* stmp = s0; s0 = s1; s1 = s2; s2 = stmp;
        const uint32_t utmp = u0; u0 = u1; u1 = u2; u2 = utmp;
    }

    // ---- combine partial rowsums ----
    lsum0 += __shfl_xor_sync(0xffffffffu, lsum0, 1);
    lsum0 += __shfl_xor_sync(0xffffffffu, lsum0, 2);
    lsum1 += __shfl_xor_sync(0xffffffffu, lsum1, 1);
    lsum1 += __shfl_xor_sync(0xffffffffu, lsum1, 2);
    float* LS = (float*)(smem + LS_OFF);
    __syncthreads();
    LS[(prow + g) * 2 + ch]     = lsum0;
    LS[(prow + 8 + g) * 2 + ch] = lsum1;
    __syncthreads();
    const float inv0 = 1.0f / (LS[(prow + g) * 2]     + LS[(prow + g) * 2 + 1]);
    const float inv1 = 1.0f / (LS[(prow + 8 + g) * 2] + LS[(prow + 8 + g) * 2 + 1]);

    // ---- epilogue (unchanged) ----
    float* Osm = (float*)smem;
    const int tl = prow + g;
    for (int cc = 0; cc < 8; cc++) {
        __syncthreads();
        if ((cc >> 2) == ch) {
#pragma unroll
            for (int nbl = 0; nbl < 4; nbl++) {
                const int nb = (cc & 3) * 4 + nbl;
                const int c0 = nbl * 8 + 2 * tig;
                Osm[(c0 + 0) * 132 + tl]     = acc[nb][0] * inv0;
                Osm[(c0 + 1) * 132 + tl]     = acc[nb][1] * inv0;
                Osm[(c0 + 0) * 132 + tl + 8] = acc[nb][2] * inv1;
                Osm[(c0 + 1) * 132 + tl + 8] = acc[nb][3] * inv1;
            }
        }
        __syncthreads();
#pragma unroll
        for (int k = 0; k < 2; k++) {
            const int i = tid + k * 512;
            const int c = i >> 5;
            const int t4 = i & 31;
            float4 v = *(const float4*)&Osm[c * 132 + t4 * 4];
            const size_t gi = ((size_t)b * C_ + cc * 32 + c) * T_ + t0 + t4 * 4;
            const float4 xv = *(const float4*)&x[gi];
            v.x += xv.x; v.y += xv.y; v.z += xv.z; v.w += xv.w;
            *(float4*)&out[gi] = v;
        }
    }
}

// ===========================================================================
extern "C" void kernel_launch(void* const* d_in, const int* in_sizes, int n_in,
                              void* d_out, int out_size)
{
    const float* x  = (const float*)d_in[0];
    const float* Wq = (const float*)d_in[1];
    const float* bq = (const float*)d_in[2];
    const float* Wk = (const float*)d_in[3];
    const float* bk = (const float*)d_in[4];
    const float* Wv = (const float*)d_in[5];
    const float* bv = (const float*)d_in[6];
    float* out = (float*)d_out;

    void *qp, *kp, *vp;
    cudaGetSymbolAddress(&qp, g_Q);
    cudaGetSymbolAddress(&kp, g_K);
    cudaGetSymbolAddress(&vp, g_V);

    cudaFuncSetAttribute(attn_mma_kernel,
                         cudaFuncAttributeMaxDynamicSharedMemorySize, SMEM_BYTES);
    cudaFuncSetAttribute(vproj_mma_kernel,
                         cudaFuncAttributeMaxDynamicSharedMemorySize, VP_SMEM);

    wpack_kernel<<<C_ * C_ / 256, 256>>>(Wv);
    qkproj_kernel<<<dim3(T_ / 128, 1, B_), 256>>>(x, Wq, bq, Wk, bk,
                                                  (float*)qp, (float*)kp);
    vproj_mma_kernel<<<dim3(T_ / 128, B_), 512, VP_SMEM>>>(
        x, bv, (__nv_bfloat16*)vp);
    attn_mma_kernel<<<dim3(T_ / 128, B_), 512, SMEM_BYTES>>>(x, out);
}